// round 1
// baseline (speedup 1.0000x reference)
#include <cuda_runtime.h>
#include <math.h>

#define SEQ   4096
#define HID   2048
#define NE    8
#define FFN   1408
#define FFN2  2816
#define CAP   4096

#define BM 64
#define BN 64
#define BK 16

// ---- scratch (static device globals; no allocation allowed) ----
__device__ int   g_count[NE];
__device__ int   g_tok[NE * CAP];
__device__ float g_wt [NE * CAP];
__device__ float g_act[(size_t)NE * CAP * FFN];   // ~184 MB, worst-case capacity per expert

// ---------------------------------------------------------------------------
// Zero the final_hidden_states region + per-expert counters.
// ---------------------------------------------------------------------------
__global__ void reset_kernel(float4* __restrict__ out) {
    size_t n = (size_t)SEQ * HID / 4;
    for (size_t i = (size_t)blockIdx.x * blockDim.x + threadIdx.x; i < n;
         i += (size_t)gridDim.x * blockDim.x)
        out[i] = make_float4(0.f, 0.f, 0.f, 0.f);
    if (blockIdx.x == 0 && threadIdx.x < NE) g_count[threadIdx.x] = 0;
}

// ---------------------------------------------------------------------------
// Router: one warp per token. logits = x @ gate_w, softmax, top-2, normalized
// weights; append (token, weight) to the chosen experts' lists.
// ---------------------------------------------------------------------------
__global__ void router_kernel(const float* __restrict__ X,
                              const float* __restrict__ G,
                              float* __restrict__ out_logits) {
    int warp = (blockIdx.x * blockDim.x + threadIdx.x) >> 5;
    int lane = threadIdx.x & 31;
    if (warp >= SEQ) return;

    const float* x = X + (size_t)warp * HID;
    float acc[NE];
#pragma unroll
    for (int e = 0; e < NE; e++) acc[e] = 0.f;

    for (int h = lane; h < HID; h += 32) {
        float xv = x[h];
        const float* g = G + (size_t)h * NE;
#pragma unroll
        for (int e = 0; e < NE; e++) acc[e] += xv * g[e];
    }
#pragma unroll
    for (int e = 0; e < NE; e++) {
#pragma unroll
        for (int o = 16; o > 0; o >>= 1)
            acc[e] += __shfl_xor_sync(0xFFFFFFFFu, acc[e], o);
    }

    if (lane == 0) {
        if (out_logits) {
#pragma unroll
            for (int e = 0; e < NE; e++) out_logits[warp * NE + e] = acc[e];
        }
        // softmax (normalizer cancels in top-2 renorm, but compute p anyway)
        float m = acc[0];
#pragma unroll
        for (int e = 1; e < NE; e++) m = fmaxf(m, acc[e]);
        float p[NE];
#pragma unroll
        for (int e = 0; e < NE; e++) p[e] = __expf(acc[e] - m);

        int i1 = 0;
#pragma unroll
        for (int e = 1; e < NE; e++) if (p[e] > p[i1]) i1 = e;
        int i2 = (i1 == 0) ? 1 : 0;
#pragma unroll
        for (int e = 0; e < NE; e++)
            if (e != i1 && p[e] > p[i2]) i2 = e;

        float tot = p[i1] + p[i2];
        float w1 = p[i1] / tot;
        float w2 = p[i2] / tot;

        int s1 = atomicAdd(&g_count[i1], 1);
        g_tok[i1 * CAP + s1] = warp;
        g_wt [i1 * CAP + s1] = w1;
        int s2 = atomicAdd(&g_count[i2], 1);
        g_tok[i2 * CAP + s2] = warp;
        g_wt [i2 * CAP + s2] = w2;
    }
}

// ---------------------------------------------------------------------------
// GEMM1: per expert, for its assigned tokens:
//   g = X @ w1[e, 0:F]^T, u = X @ w1[e, F:2F]^T, act = silu(g)*u  -> g_act
// Tile 64x64x16, 256 threads, 4x4 microtile per thread (dual accumulators).
// ---------------------------------------------------------------------------
__global__ void __launch_bounds__(256)
gemm1_kernel(const float* __restrict__ X, const float* __restrict__ W1) {
    int e   = blockIdx.z;
    int cnt = g_count[e];
    int row0 = blockIdx.x * BM;
    if (row0 >= cnt) return;
    int col0 = blockIdx.y * BN;

    __shared__ float As[BK][BM];
    __shared__ float Bg[BK][BN];
    __shared__ float Bu[BK][BN];

    int tid  = threadIdx.x;
    int tx   = tid & 15;
    int ty   = tid >> 4;
    int lrow = tid >> 2;          // 0..63
    int lk   = (tid & 3) * 4;     // 0,4,8,12

    int arow = row0 + lrow;
    int tokA = g_tok[e * CAP + min(arow, cnt - 1)];
    const float* aptr  = X  + (size_t)tokA * HID + lk;
    const float* bgptr = W1 + ((size_t)e * FFN2 + (col0 + lrow)) * HID + lk;
    const float* buptr = W1 + ((size_t)e * FFN2 + FFN + (col0 + lrow)) * HID + lk;

    float accg[4][4] = {};
    float accu[4][4] = {};

    for (int k0 = 0; k0 < HID; k0 += BK) {
        float4 a  = *(const float4*)(aptr  + k0);
        float4 bg = *(const float4*)(bgptr + k0);
        float4 bu = *(const float4*)(buptr + k0);
        As[lk + 0][lrow] = a.x;  As[lk + 1][lrow] = a.y;
        As[lk + 2][lrow] = a.z;  As[lk + 3][lrow] = a.w;
        Bg[lk + 0][lrow] = bg.x; Bg[lk + 1][lrow] = bg.y;
        Bg[lk + 2][lrow] = bg.z; Bg[lk + 3][lrow] = bg.w;
        Bu[lk + 0][lrow] = bu.x; Bu[lk + 1][lrow] = bu.y;
        Bu[lk + 2][lrow] = bu.z; Bu[lk + 3][lrow] = bu.w;
        __syncthreads();

#pragma unroll
        for (int kk = 0; kk < BK; kk++) {
            float4 av  = *(const float4*)&As[kk][ty * 4];
            float4 bgv = *(const float4*)&Bg[kk][tx * 4];
            float4 buv = *(const float4*)&Bu[kk][tx * 4];
            float a_[4]  = {av.x,  av.y,  av.z,  av.w};
            float bg_[4] = {bgv.x, bgv.y, bgv.z, bgv.w};
            float bu_[4] = {buv.x, buv.y, buv.z, buv.w};
#pragma unroll
            for (int i = 0; i < 4; i++)
#pragma unroll
                for (int j = 0; j < 4; j++) {
                    accg[i][j] += a_[i] * bg_[j];
                    accu[i][j] += a_[i] * bu_[j];
                }
        }
        __syncthreads();
    }

#pragma unroll
    for (int i = 0; i < 4; i++) {
        int r = row0 + ty * 4 + i;
        if (r < cnt) {
            float4 o;
            float g0 = accg[i][0], g1 = accg[i][1], g2 = accg[i][2], g3 = accg[i][3];
            o.x = (g0 / (1.f + __expf(-g0))) * accu[i][0];
            o.y = (g1 / (1.f + __expf(-g1))) * accu[i][1];
            o.z = (g2 / (1.f + __expf(-g2))) * accu[i][2];
            o.w = (g3 / (1.f + __expf(-g3))) * accu[i][3];
            *(float4*)(g_act + ((size_t)e * CAP + r) * FFN + col0 + tx * 4) = o;
        }
    }
}

// ---------------------------------------------------------------------------
// GEMM2: y = act @ w2[e]^T, then out[token] += routing_weight * y (atomic).
// ---------------------------------------------------------------------------
__global__ void __launch_bounds__(256)
gemm2_kernel(const float* __restrict__ W2, float* __restrict__ out) {
    int e   = blockIdx.z;
    int cnt = g_count[e];
    int row0 = blockIdx.x * BM;
    if (row0 >= cnt) return;
    int col0 = blockIdx.y * BN;

    __shared__ float As[BK][BM];
    __shared__ float Bs[BK][BN];

    int tid  = threadIdx.x;
    int tx   = tid & 15;
    int ty   = tid >> 4;
    int lrow = tid >> 2;
    int lk   = (tid & 3) * 4;

    int arow = min(row0 + lrow, cnt - 1);
    const float* aptr = g_act + ((size_t)e * CAP + arow) * FFN + lk;
    const float* bptr = W2 + ((size_t)e * HID + (col0 + lrow)) * FFN + lk;

    float acc[4][4] = {};

    for (int k0 = 0; k0 < FFN; k0 += BK) {
        float4 a = *(const float4*)(aptr + k0);
        float4 b = *(const float4*)(bptr + k0);
        As[lk + 0][lrow] = a.x; As[lk + 1][lrow] = a.y;
        As[lk + 2][lrow] = a.z; As[lk + 3][lrow] = a.w;
        Bs[lk + 0][lrow] = b.x; Bs[lk + 1][lrow] = b.y;
        Bs[lk + 2][lrow] = b.z; Bs[lk + 3][lrow] = b.w;
        __syncthreads();

#pragma unroll
        for (int kk = 0; kk < BK; kk++) {
            float4 av = *(const float4*)&As[kk][ty * 4];
            float4 bv = *(const float4*)&Bs[kk][tx * 4];
            float a_[4] = {av.x, av.y, av.z, av.w};
            float b_[4] = {bv.x, bv.y, bv.z, bv.w};
#pragma unroll
            for (int i = 0; i < 4; i++)
#pragma unroll
                for (int j = 0; j < 4; j++)
                    acc[i][j] += a_[i] * b_[j];
        }
        __syncthreads();
    }

#pragma unroll
    for (int i = 0; i < 4; i++) {
        int r = row0 + ty * 4 + i;
        if (r < cnt) {
            int   tok = g_tok[e * CAP + r];
            float w   = g_wt [e * CAP + r];
            float* dst = out + (size_t)tok * HID + col0 + tx * 4;
#pragma unroll
            for (int j = 0; j < 4; j++)
                atomicAdd(dst + j, w * acc[i][j]);
        }
    }
}

// ---------------------------------------------------------------------------
extern "C" void kernel_launch(void* const* d_in, const int* in_sizes, int n_in,
                              void* d_out, int out_size) {
    const float* X  = (const float*)d_in[0];   // [SEQ, HID]
    const float* G  = (const float*)d_in[1];   // [HID, NE]
    const float* W1 = (const float*)d_in[2];   // [NE, 2F, HID]
    const float* W2 = (const float*)d_in[3];   // [NE, HID, F]
    float* out = (float*)d_out;

    bool has_logits = (long long)out_size >= (long long)SEQ * HID + (long long)SEQ * NE;
    float* logits = has_logits ? out + (size_t)SEQ * HID : nullptr;

    reset_kernel<<<2048, 256>>>((float4*)out);
    router_kernel<<<SEQ / 8, 256>>>(X, G, logits);
    gemm1_kernel<<<dim3(CAP / BM, FFN / BN, NE), 256>>>(X, W1);
    gemm2_kernel<<<dim3(CAP / BM, HID / BN, NE), 256>>>(W2, out);
}

// round 5
// speedup vs baseline: 2.5951x; 2.5951x over previous
#include <cuda_runtime.h>
#include <cuda_bf16.h>
#include <cstdint>
#include <math.h>

#define SEQ   4096
#define HID   2048
#define NE    8
#define FFN   1408
#define FFN2  2816
#define CAP   4096

// ---------------- static scratch ----------------
__device__ int   g_count[NE];
__device__ int   g_tok [NE * CAP];
__device__ int   g_slot[NE * CAP];
__device__ float g_twt [SEQ * 2];

__device__ __nv_bfloat16 g_Xhi [(size_t)SEQ * HID];
__device__ __nv_bfloat16 g_Xlo [(size_t)SEQ * HID];
__device__ __nv_bfloat16 g_W1hi[(size_t)NE * FFN2 * HID];
__device__ __nv_bfloat16 g_W1lo[(size_t)NE * FFN2 * HID];
__device__ __nv_bfloat16 g_W2hi[(size_t)NE * HID * FFN];
__device__ __nv_bfloat16 g_W2lo[(size_t)NE * HID * FFN];
__device__ float         g_H   [(size_t)NE * CAP * FFN2];  // raw gate|up
__device__ __nv_bfloat16 g_Ahi [(size_t)NE * CAP * FFN];
__device__ __nv_bfloat16 g_Alo [(size_t)NE * CAP * FFN];
__device__ float         g_Y   [(size_t)2 * SEQ * HID];    // per-slot outputs

// ---------------- helpers ----------------
__device__ __forceinline__ uint32_t smem_u32(const void* p) {
    uint32_t a;
    asm("{ .reg .u64 t; cvta.to.shared.u64 t, %1; cvt.u32.u64 %0, t; }"
        : "=r"(a) : "l"(p));
    return a;
}
__device__ __forceinline__ void cpa16(uint32_t dst, const void* src) {
    asm volatile("cp.async.cg.shared.global [%0], [%1], 16;" :: "r"(dst), "l"(src));
}
#define CP_COMMIT() asm volatile("cp.async.commit_group;" ::: "memory")
#define CP_WAIT1()  asm volatile("cp.async.wait_group 1;" ::: "memory")

__device__ __forceinline__ void ldsm4(uint32_t& r0, uint32_t& r1, uint32_t& r2,
                                      uint32_t& r3, uint32_t addr) {
    asm volatile("ldmatrix.sync.aligned.m8n8.x4.shared.b16 {%0,%1,%2,%3}, [%4];"
                 : "=r"(r0), "=r"(r1), "=r"(r2), "=r"(r3) : "r"(addr));
}
__device__ __forceinline__ void mma16816(float* c, const uint32_t* a,
                                         uint32_t b0, uint32_t b1) {
    asm volatile(
        "mma.sync.aligned.m16n8k16.row.col.f32.bf16.bf16.f32 "
        "{%0,%1,%2,%3}, {%4,%5,%6,%7}, {%8,%9}, {%0,%1,%2,%3};"
        : "+f"(c[0]), "+f"(c[1]), "+f"(c[2]), "+f"(c[3])
        : "r"(a[0]), "r"(a[1]), "r"(a[2]), "r"(a[3]), "r"(b0), "r"(b1));
}

// smem tile geometry: 128 rows x 32 k-elems, padded to 40 elems (80B) per row
#define SROW   40
#define TILEB  (128 * SROW * 2)   // 10240 B per array
#define BUFB   (4 * TILEB)        // Ah, Al, Bh, Bl
#define GSMEM  (2 * BUFB)         // double buffered = 81920 B

// ---------------------------------------------------------------------------
__global__ void reset_kernel() {
    if (threadIdx.x < NE) g_count[threadIdx.x] = 0;
}

// ---------------------------------------------------------------------------
__global__ void split_kernel(const float4* __restrict__ src, size_t n4, int which) {
    __nv_bfloat16 *hi, *lo;
    if (which == 0)      { hi = g_Xhi;  lo = g_Xlo;  }
    else if (which == 1) { hi = g_W1hi; lo = g_W1lo; }
    else                 { hi = g_W2hi; lo = g_W2lo; }
    uint2* dh = (uint2*)hi;
    uint2* dl = (uint2*)lo;
    for (size_t i = (size_t)blockIdx.x * blockDim.x + threadIdx.x; i < n4;
         i += (size_t)gridDim.x * blockDim.x) {
        float4 v = src[i];
        __nv_bfloat162 h01 = __floats2bfloat162_rn(v.x, v.y);
        __nv_bfloat162 h23 = __floats2bfloat162_rn(v.z, v.w);
        float rx = v.x - __bfloat162float(__low2bfloat16(h01));
        float ry = v.y - __bfloat162float(__high2bfloat16(h01));
        float rz = v.z - __bfloat162float(__low2bfloat16(h23));
        float rw = v.w - __bfloat162float(__high2bfloat16(h23));
        __nv_bfloat162 l01 = __floats2bfloat162_rn(rx, ry);
        __nv_bfloat162 l23 = __floats2bfloat162_rn(rz, rw);
        uint2 uh, ul;
        uh.x = *(uint32_t*)&h01; uh.y = *(uint32_t*)&h23;
        ul.x = *(uint32_t*)&l01; ul.y = *(uint32_t*)&l23;
        dh[i] = uh; dl[i] = ul;
    }
}

// ---------------------------------------------------------------------------
__global__ void router_kernel(const float* __restrict__ X,
                              const float* __restrict__ G,
                              float* __restrict__ out_logits) {
    int warp = (blockIdx.x * blockDim.x + threadIdx.x) >> 5;
    int lane = threadIdx.x & 31;
    if (warp >= SEQ) return;

    const float* x = X + (size_t)warp * HID;
    float acc[NE];
#pragma unroll
    for (int e = 0; e < NE; e++) acc[e] = 0.f;
    for (int h = lane; h < HID; h += 32) {
        float xv = x[h];
        const float* g = G + (size_t)h * NE;
#pragma unroll
        for (int e = 0; e < NE; e++) acc[e] += xv * g[e];
    }
#pragma unroll
    for (int e = 0; e < NE; e++)
#pragma unroll
        for (int o = 16; o > 0; o >>= 1)
            acc[e] += __shfl_xor_sync(0xFFFFFFFFu, acc[e], o);

    if (lane == 0) {
        if (out_logits) {
#pragma unroll
            for (int e = 0; e < NE; e++) out_logits[warp * NE + e] = acc[e];
        }
        float m = acc[0];
#pragma unroll
        for (int e = 1; e < NE; e++) m = fmaxf(m, acc[e]);
        float p[NE];
#pragma unroll
        for (int e = 0; e < NE; e++) p[e] = __expf(acc[e] - m);
        int i1 = 0;
#pragma unroll
        for (int e = 1; e < NE; e++) if (p[e] > p[i1]) i1 = e;
        int i2 = (i1 == 0) ? 1 : 0;
#pragma unroll
        for (int e = 0; e < NE; e++)
            if (e != i1 && p[e] > p[i2]) i2 = e;
        float tot = p[i1] + p[i2];
        g_twt[warp * 2 + 0] = p[i1] / tot;
        g_twt[warp * 2 + 1] = p[i2] / tot;
        int s1 = atomicAdd(&g_count[i1], 1);
        g_tok [i1 * CAP + s1] = warp;
        g_slot[i1 * CAP + s1] = 0;
        int s2 = atomicAdd(&g_count[i2], 1);
        g_tok [i2 * CAP + s2] = warp;
        g_slot[i2 * CAP + s2] = 1;
    }
}

// ---------------------------------------------------------------------------
// GEMM core (shared by both GEMMs through a macro-ish structure)
// CTA: 128 rows x 128 cols, K-blocks of 32. 8 warps, warp tile 32x64.
// ---------------------------------------------------------------------------
struct FragAddr {
    uint32_t aoff;   // A frag base (k16=0) within buffer, bytes
    uint32_t boff;   // B frag base (pair 0, k16=0) within buffer, bytes
};
__device__ __forceinline__ FragAddr frag_addrs(int tid) {
    int lane = tid & 31, wid = tid >> 5;
    int wm = wid >> 1, wn = wid & 1;
    int t = lane >> 3, l7 = lane & 7;
    FragAddr f;
    f.aoff = (uint32_t)((wm * 32 + (t & 1) * 8 + l7) * (SROW * 2) + (t >> 1) * 16);
    f.boff = (uint32_t)((wn * 64 + (t >> 1) * 8 + l7) * (SROW * 2) + (t & 1) * 16)
             + 2 * TILEB;
    return f;
}

// compute one k-block (32) for warp-tile accumulators
__device__ __forceinline__ void compute_kb(uint32_t base, const FragAddr& f,
                                           float acc[2][8][4]) {
#pragma unroll
    for (int k16 = 0; k16 < 2; k16++) {
        uint32_t koff = k16 * 32;
        uint32_t ah[2][4], al[2][4];
        ldsm4(ah[0][0], ah[0][1], ah[0][2], ah[0][3], base + f.aoff + koff);
        ldsm4(ah[1][0], ah[1][1], ah[1][2], ah[1][3], base + f.aoff + koff + 16 * SROW * 2);
        ldsm4(al[0][0], al[0][1], al[0][2], al[0][3], base + TILEB + f.aoff + koff);
        ldsm4(al[1][0], al[1][1], al[1][2], al[1][3], base + TILEB + f.aoff + koff + 16 * SROW * 2);
        uint32_t bh[4][4], bl[4][4];
#pragma unroll
        for (int p = 0; p < 4; p++) {
            uint32_t po = p * 16 * SROW * 2;
            ldsm4(bh[p][0], bh[p][1], bh[p][2], bh[p][3], base + f.boff + po + koff);
            ldsm4(bl[p][0], bl[p][1], bl[p][2], bl[p][3], base + TILEB + f.boff + po + koff);
        }
#pragma unroll
        for (int mi = 0; mi < 2; mi++)
#pragma unroll
            for (int ni = 0; ni < 8; ni++) {
                int p = ni >> 1, q = (ni & 1) * 2;
                mma16816(acc[mi][ni], ah[mi], bh[p][q], bh[p][q + 1]);
                mma16816(acc[mi][ni], ah[mi], bl[p][q], bl[p][q + 1]);
                mma16816(acc[mi][ni], al[mi], bh[p][q], bh[p][q + 1]);
            }
    }
}

// ---------------------------------------------------------------------------
#define NKB1 (HID / 32)
__global__ void __launch_bounds__(256, 1) gemm1_kernel() {
    extern __shared__ char smem[];
    int e = blockIdx.z;
    int cnt = g_count[e];
    int row0 = blockIdx.x * 128;
    if (row0 >= cnt) return;
    int col0 = blockIdx.y * 128;

    int tid = threadIdx.x;
    uint32_t sb = smem_u32(smem);

    // loader: thread -> (row, half)
    int lrow = tid >> 1, h = tid & 1;
    int tokA = g_tok[e * CAP + min(row0 + lrow, cnt - 1)];
    const __nv_bfloat16* sAh = g_Xhi + (size_t)tokA * HID + h * 16;
    const __nv_bfloat16* sAl = g_Xlo + (size_t)tokA * HID + h * 16;
    size_t wrow = ((size_t)e * FFN2 + col0 + lrow) * HID;
    const __nv_bfloat16* sBh = g_W1hi + wrow + h * 16;
    const __nv_bfloat16* sBl = g_W1lo + wrow + h * 16;
    uint32_t dsto = (uint32_t)(lrow * (SROW * 2) + h * 32);

#define G1_ISSUE(kb)                                                        \
    do {                                                                    \
        if ((kb) < NKB1) {                                                  \
            uint32_t d = sb + ((kb) & 1) * BUFB + dsto;                     \
            int k0 = (kb) * 32;                                             \
            cpa16(d,                 sAh + k0); cpa16(d + 16,                 sAh + k0 + 8); \
            cpa16(d + TILEB,         sAl + k0); cpa16(d + TILEB + 16,         sAl + k0 + 8); \
            cpa16(d + 2 * TILEB,     sBh + k0); cpa16(d + 2 * TILEB + 16,     sBh + k0 + 8); \
            cpa16(d + 3 * TILEB,     sBl + k0); cpa16(d + 3 * TILEB + 16,     sBl + k0 + 8); \
        }                                                                   \
        CP_COMMIT();                                                        \
    } while (0)

    G1_ISSUE(0);
    G1_ISSUE(1);

    FragAddr f = frag_addrs(tid);
    float acc[2][8][4];
#pragma unroll
    for (int mi = 0; mi < 2; mi++)
#pragma unroll
        for (int ni = 0; ni < 8; ni++)
#pragma unroll
            for (int q = 0; q < 4; q++) acc[mi][ni][q] = 0.f;

    for (int kb = 0; kb < NKB1; kb++) {
        CP_WAIT1();
        __syncthreads();
        compute_kb(sb + (kb & 1) * BUFB, f, acc);
        __syncthreads();
        G1_ISSUE(kb + 2);
    }

    // epilogue: raw fp32 to g_H
    int lane = tid & 31, wid = tid >> 5;
    int wm = wid >> 1, wn = wid & 1;
    int gid = lane >> 2, t4 = lane & 3;
#pragma unroll
    for (int mi = 0; mi < 2; mi++) {
        int r0 = row0 + wm * 32 + mi * 16 + gid;
#pragma unroll
        for (int ni = 0; ni < 8; ni++) {
            int col = col0 + wn * 64 + ni * 8 + 2 * t4;
            if (r0 < cnt) {
                float2 v = make_float2(acc[mi][ni][0], acc[mi][ni][1]);
                *(float2*)(g_H + ((size_t)e * CAP + r0) * FFN2 + col) = v;
            }
            if (r0 + 8 < cnt) {
                float2 v = make_float2(acc[mi][ni][2], acc[mi][ni][3]);
                *(float2*)(g_H + ((size_t)e * CAP + r0 + 8) * FFN2 + col) = v;
            }
        }
    }
#undef G1_ISSUE
}

// ---------------------------------------------------------------------------
#define NKB2 (FFN / 32)
__global__ void __launch_bounds__(256, 1) gemm2_kernel() {
    extern __shared__ char smem[];
    int e = blockIdx.z;
    int cnt = g_count[e];
    int row0 = blockIdx.x * 128;
    if (row0 >= cnt) return;
    int col0 = blockIdx.y * 128;

    int tid = threadIdx.x;
    uint32_t sb = smem_u32(smem);

    int lrow = tid >> 1, h = tid & 1;
    size_t arow = ((size_t)e * CAP + min(row0 + lrow, cnt - 1)) * FFN;
    const __nv_bfloat16* sAh = g_Ahi + arow + h * 16;
    const __nv_bfloat16* sAl = g_Alo + arow + h * 16;
    size_t wrow = ((size_t)e * HID + col0 + lrow) * FFN;
    const __nv_bfloat16* sBh = g_W2hi + wrow + h * 16;
    const __nv_bfloat16* sBl = g_W2lo + wrow + h * 16;
    uint32_t dsto = (uint32_t)(lrow * (SROW * 2) + h * 32);

#define G2_ISSUE(kb)                                                        \
    do {                                                                    \
        if ((kb) < NKB2) {                                                  \
            uint32_t d = sb + ((kb) & 1) * BUFB + dsto;                     \
            int k0 = (kb) * 32;                                             \
            cpa16(d,                 sAh + k0); cpa16(d + 16,                 sAh + k0 + 8); \
            cpa16(d + TILEB,         sAl + k0); cpa16(d + TILEB + 16,         sAl + k0 + 8); \
            cpa16(d + 2 * TILEB,     sBh + k0); cpa16(d + 2 * TILEB + 16,     sBh + k0 + 8); \
            cpa16(d + 3 * TILEB,     sBl + k0); cpa16(d + 3 * TILEB + 16,     sBl + k0 + 8); \
        }                                                                   \
        CP_COMMIT();                                                        \
    } while (0)

    G2_ISSUE(0);
    G2_ISSUE(1);

    FragAddr f = frag_addrs(tid);
    float acc[2][8][4];
#pragma unroll
    for (int mi = 0; mi < 2; mi++)
#pragma unroll
        for (int ni = 0; ni < 8; ni++)
#pragma unroll
            for (int q = 0; q < 4; q++) acc[mi][ni][q] = 0.f;

    for (int kb = 0; kb < NKB2; kb++) {
        CP_WAIT1();
        __syncthreads();
        compute_kb(sb + (kb & 1) * BUFB, f, acc);
        __syncthreads();
        G2_ISSUE(kb + 2);
    }

    // epilogue: store to per-slot Y buffers (no atomics)
    int lane = tid & 31, wid = tid >> 5;
    int wm = wid >> 1, wn = wid & 1;
    int gid = lane >> 2, t4 = lane & 3;
#pragma unroll
    for (int mi = 0; mi < 2; mi++) {
        int r0 = row0 + wm * 32 + mi * 16 + gid;
        int r1 = r0 + 8;
        int   tok0 = 0, slot0 = 0, tok1 = 0, slot1 = 0;
        if (r0 < cnt) { tok0 = g_tok[e * CAP + r0]; slot0 = g_slot[e * CAP + r0]; }
        if (r1 < cnt) { tok1 = g_tok[e * CAP + r1]; slot1 = g_slot[e * CAP + r1]; }
#pragma unroll
        for (int ni = 0; ni < 8; ni++) {
            int col = col0 + wn * 64 + ni * 8 + 2 * t4;
            if (r0 < cnt) {
                float2 v = make_float2(acc[mi][ni][0], acc[mi][ni][1]);
                *(float2*)(g_Y + ((size_t)slot0 * SEQ + tok0) * HID + col) = v;
            }
            if (r1 < cnt) {
                float2 v = make_float2(acc[mi][ni][2], acc[mi][ni][3]);
                *(float2*)(g_Y + ((size_t)slot1 * SEQ + tok1) * HID + col) = v;
            }
        }
    }
#undef G2_ISSUE
}

// ---------------------------------------------------------------------------
// activation: act = silu(gate) * up, split to bf16 hi/lo
// ---------------------------------------------------------------------------
__global__ void act_kernel() {
    int e = blockIdx.y;
    int r = blockIdx.x;
    if (r >= g_count[e]) return;
    const float4* g4 = (const float4*)(g_H + ((size_t)e * CAP + r) * FFN2);
    const float4* u4 = g4 + FFN / 4;
    uint2* dh = (uint2*)(g_Ahi + ((size_t)e * CAP + r) * FFN);
    uint2* dl = (uint2*)(g_Alo + ((size_t)e * CAP + r) * FFN);
    for (int c = threadIdx.x; c < FFN / 4; c += blockDim.x) {
        float4 g = g4[c], u = u4[c];
        float a0 = g.x / (1.f + __expf(-g.x)) * u.x;
        float a1 = g.y / (1.f + __expf(-g.y)) * u.y;
        float a2 = g.z / (1.f + __expf(-g.z)) * u.z;
        float a3 = g.w / (1.f + __expf(-g.w)) * u.w;
        __nv_bfloat162 h01 = __floats2bfloat162_rn(a0, a1);
        __nv_bfloat162 h23 = __floats2bfloat162_rn(a2, a3);
        float r0 = a0 - __bfloat162float(__low2bfloat16(h01));
        float r1 = a1 - __bfloat162float(__high2bfloat16(h01));
        float r2 = a2 - __bfloat162float(__low2bfloat16(h23));
        float r3 = a3 - __bfloat162float(__high2bfloat16(h23));
        __nv_bfloat162 l01 = __floats2bfloat162_rn(r0, r1);
        __nv_bfloat162 l23 = __floats2bfloat162_rn(r2, r3);
        uint2 uh, ul;
        uh.x = *(uint32_t*)&h01; uh.y = *(uint32_t*)&h23;
        ul.x = *(uint32_t*)&l01; ul.y = *(uint32_t*)&l23;
        dh[c] = uh; dl[c] = ul;
    }
}

// ---------------------------------------------------------------------------
__global__ void combine_kernel(float4* __restrict__ out) {
    const float4* y = (const float4*)g_Y;
    size_t n = (size_t)SEQ * HID / 4;
    for (size_t i = (size_t)blockIdx.x * blockDim.x + threadIdx.x; i < n;
         i += (size_t)gridDim.x * blockDim.x) {
        int t = (int)(i >> (9));   // HID/4 = 512 float4 per token
        float w0 = g_twt[t * 2 + 0];
        float w1 = g_twt[t * 2 + 1];
        float4 a = y[i];
        float4 b = y[i + n];
        float4 o;
        o.x = w0 * a.x + w1 * b.x;
        o.y = w0 * a.y + w1 * b.y;
        o.z = w0 * a.z + w1 * b.z;
        o.w = w0 * a.w + w1 * b.w;
        out[i] = o;
    }
}

// ---------------------------------------------------------------------------
extern "C" void kernel_launch(void* const* d_in, const int* in_sizes, int n_in,
                              void* d_out, int out_size) {
    const float* X  = (const float*)d_in[0];
    const float* G  = (const float*)d_in[1];
    const float* W1 = (const float*)d_in[2];
    const float* W2 = (const float*)d_in[3];
    float* out = (float*)d_out;

    bool has_logits = (long long)out_size >= (long long)SEQ * HID + (long long)SEQ * NE;
    float* logits = has_logits ? out + (size_t)SEQ * HID : nullptr;

    cudaFuncSetAttribute(gemm1_kernel, cudaFuncAttributeMaxDynamicSharedMemorySize, GSMEM);
    cudaFuncSetAttribute(gemm2_kernel, cudaFuncAttributeMaxDynamicSharedMemorySize, GSMEM);

    reset_kernel<<<1, 32>>>();
    router_kernel<<<SEQ / 8, 256>>>(X, G, logits);
    split_kernel<<<2048, 256>>>((const float4*)X,  (size_t)SEQ * HID / 4, 0);
    split_kernel<<<4096, 256>>>((const float4*)W1, (size_t)NE * FFN2 * HID / 4, 1);
    split_kernel<<<4096, 256>>>((const float4*)W2, (size_t)NE * HID * FFN / 4, 2);
    gemm1_kernel<<<dim3(CAP / 128, FFN2 / 128, NE), 256, GSMEM>>>();
    act_kernel<<<dim3(CAP, NE), 128>>>();
    gemm2_kernel<<<dim3(CAP / 128, HID / 128, NE), 256, GSMEM>>>();
    combine_kernel<<<4096, 256>>>((float4*)out);
}

// round 6
// speedup vs baseline: 3.0819x; 1.1876x over previous
#include <cuda_runtime.h>
#include <cuda_fp16.h>
#include <cstdint>
#include <math.h>

#define SEQ   4096
#define HID   2048
#define NE    8
#define FFN   1408
#define FFN2  2816
#define CAP   4096

// ---------------- static scratch ----------------
__device__ int   g_count[NE];
__device__ int   g_tok [NE * CAP];
__device__ int   g_slot[NE * CAP];
__device__ float g_twt [SEQ * 2];

__device__ __half g_Xhi[(size_t)SEQ * HID];
__device__ __half g_Xlo[(size_t)SEQ * HID];
__device__ __half g_W1h[(size_t)NE * FFN2 * HID];
__device__ __half g_W2h[(size_t)NE * HID * FFN];
__device__ __half g_Ahi[(size_t)NE * CAP * FFN];
__device__ __half g_Alo[(size_t)NE * CAP * FFN];
__device__ float  g_Y  [(size_t)2 * SEQ * HID];

// ---------------- helpers ----------------
__device__ __forceinline__ uint32_t smem_u32(const void* p) {
    uint32_t a;
    asm("{ .reg .u64 t; cvta.to.shared.u64 t, %1; cvt.u32.u64 %0, t; }"
        : "=r"(a) : "l"(p));
    return a;
}
__device__ __forceinline__ void cpa16(uint32_t dst, const void* src) {
    asm volatile("cp.async.cg.shared.global [%0], [%1], 16;" :: "r"(dst), "l"(src));
}
#define CP_COMMIT() asm volatile("cp.async.commit_group;" ::: "memory")
#define CP_WAIT2()  asm volatile("cp.async.wait_group 2;" ::: "memory")
#define CP_WAIT0()  asm volatile("cp.async.wait_group 0;" ::: "memory")

__device__ __forceinline__ void ldsm4(uint32_t& r0, uint32_t& r1, uint32_t& r2,
                                      uint32_t& r3, uint32_t addr) {
    asm volatile("ldmatrix.sync.aligned.m8n8.x4.shared.b16 {%0,%1,%2,%3}, [%4];"
                 : "=r"(r0), "=r"(r1), "=r"(r2), "=r"(r3) : "r"(addr));
}
__device__ __forceinline__ void mma16816(float* c, const uint32_t* a,
                                         uint32_t b0, uint32_t b1) {
    asm volatile(
        "mma.sync.aligned.m16n8k16.row.col.f32.f16.f16.f32 "
        "{%0,%1,%2,%3}, {%4,%5,%6,%7}, {%8,%9}, {%0,%1,%2,%3};"
        : "+f"(c[0]), "+f"(c[1]), "+f"(c[2]), "+f"(c[3])
        : "r"(a[0]), "r"(a[1]), "r"(a[2]), "r"(a[3]), "r"(b0), "r"(b1));
}

// smem tile: 128 rows x 32 k, padded to 40 halves (80B) per row
#define SROW   40
#define TILEB  (128 * SROW * 2)    // 10240 B
#define SBUF   (3 * TILEB)         // Ah, Al, Bh  -> 30720 B per stage
#define NSTG   3
#define GSMEM  (NSTG * SBUF)       // 92160 B (also covers 128x132 f32 = 67584)
#define ROWF   132

// ---------------------------------------------------------------------------
__global__ void reset_kernel() {
    if (threadIdx.x < NE) g_count[threadIdx.x] = 0;
}

// ---------------------------------------------------------------------------
// X -> fp16 hi + lo
__global__ void splitx_kernel(const float4* __restrict__ src, size_t n4) {
    uint2* dh = (uint2*)g_Xhi;
    uint2* dl = (uint2*)g_Xlo;
    for (size_t i = (size_t)blockIdx.x * blockDim.x + threadIdx.x; i < n4;
         i += (size_t)gridDim.x * blockDim.x) {
        float4 v = src[i];
        __half2 h01 = __floats2half2_rn(v.x, v.y);
        __half2 h23 = __floats2half2_rn(v.z, v.w);
        float rx = v.x - __low2float(h01);
        float ry = v.y - __high2float(h01);
        float rz = v.z - __low2float(h23);
        float rw = v.w - __high2float(h23);
        __half2 l01 = __floats2half2_rn(rx, ry);
        __half2 l23 = __floats2half2_rn(rz, rw);
        uint2 uh, ul;
        uh.x = *(uint32_t*)&h01; uh.y = *(uint32_t*)&h23;
        ul.x = *(uint32_t*)&l01; ul.y = *(uint32_t*)&l23;
        dh[i] = uh; dl[i] = ul;
    }
}

// weights -> fp16 round only
__global__ void conv_kernel(const float4* __restrict__ src, size_t n4, int which) {
    uint2* dst = (uint2*)(which == 1 ? g_W1h : g_W2h);
    for (size_t i = (size_t)blockIdx.x * blockDim.x + threadIdx.x; i < n4;
         i += (size_t)gridDim.x * blockDim.x) {
        float4 v = src[i];
        __half2 h01 = __floats2half2_rn(v.x, v.y);
        __half2 h23 = __floats2half2_rn(v.z, v.w);
        uint2 u;
        u.x = *(uint32_t*)&h01; u.y = *(uint32_t*)&h23;
        dst[i] = u;
    }
}

// ---------------------------------------------------------------------------
__global__ void router_kernel(const float* __restrict__ X,
                              const float* __restrict__ G,
                              float* __restrict__ out_logits) {
    int warp = (blockIdx.x * blockDim.x + threadIdx.x) >> 5;
    int lane = threadIdx.x & 31;
    if (warp >= SEQ) return;

    const float* x = X + (size_t)warp * HID;
    float acc[NE];
#pragma unroll
    for (int e = 0; e < NE; e++) acc[e] = 0.f;
    for (int h = lane; h < HID; h += 32) {
        float xv = x[h];
        const float* g = G + (size_t)h * NE;
#pragma unroll
        for (int e = 0; e < NE; e++) acc[e] += xv * g[e];
    }
#pragma unroll
    for (int e = 0; e < NE; e++)
#pragma unroll
        for (int o = 16; o > 0; o >>= 1)
            acc[e] += __shfl_xor_sync(0xFFFFFFFFu, acc[e], o);

    if (lane == 0) {
        if (out_logits) {
#pragma unroll
            for (int e = 0; e < NE; e++) out_logits[warp * NE + e] = acc[e];
        }
        float m = acc[0];
#pragma unroll
        for (int e = 1; e < NE; e++) m = fmaxf(m, acc[e]);
        float p[NE];
#pragma unroll
        for (int e = 0; e < NE; e++) p[e] = __expf(acc[e] - m);
        int i1 = 0;
#pragma unroll
        for (int e = 1; e < NE; e++) if (p[e] > p[i1]) i1 = e;
        int i2 = (i1 == 0) ? 1 : 0;
#pragma unroll
        for (int e = 0; e < NE; e++)
            if (e != i1 && p[e] > p[i2]) i2 = e;
        float tot = p[i1] + p[i2];
        g_twt[warp * 2 + 0] = p[i1] / tot;
        g_twt[warp * 2 + 1] = p[i2] / tot;
        int s1 = atomicAdd(&g_count[i1], 1);
        g_tok [i1 * CAP + s1] = warp;
        g_slot[i1 * CAP + s1] = 0;
        int s2 = atomicAdd(&g_count[i2], 1);
        g_tok [i2 * CAP + s2] = warp;
        g_slot[i2 * CAP + s2] = 1;
    }
}

// ---------------------------------------------------------------------------
// GEMM core: CTA 128x128, kblock 32, 8 warps (warp tile 32x64), fp16 2-MMA.
// ---------------------------------------------------------------------------
struct FragAddr { uint32_t aoff, boff; };
__device__ __forceinline__ FragAddr frag_addrs(int tid) {
    int lane = tid & 31, wid = tid >> 5;
    int wm = wid >> 1, wn = wid & 1;
    int t = lane >> 3, l7 = lane & 7;
    FragAddr f;
    f.aoff = (uint32_t)((wm * 32 + (t & 1) * 8 + l7) * (SROW * 2) + (t >> 1) * 16);
    f.boff = (uint32_t)((wn * 64 + (t >> 1) * 8 + l7) * (SROW * 2) + (t & 1) * 16)
             + 2 * TILEB;
    return f;
}

__device__ __forceinline__ void compute_kb(uint32_t base, const FragAddr& f,
                                           float acc[2][8][4]) {
#pragma unroll
    for (int k16 = 0; k16 < 2; k16++) {
        uint32_t koff = k16 * 32;
        uint32_t ah[2][4], al[2][4];
        ldsm4(ah[0][0], ah[0][1], ah[0][2], ah[0][3], base + f.aoff + koff);
        ldsm4(ah[1][0], ah[1][1], ah[1][2], ah[1][3], base + f.aoff + koff + 16 * SROW * 2);
        ldsm4(al[0][0], al[0][1], al[0][2], al[0][3], base + TILEB + f.aoff + koff);
        ldsm4(al[1][0], al[1][1], al[1][2], al[1][3], base + TILEB + f.aoff + koff + 16 * SROW * 2);
        uint32_t bh[4][4];
#pragma unroll
        for (int p = 0; p < 4; p++) {
            uint32_t po = p * 16 * SROW * 2;
            ldsm4(bh[p][0], bh[p][1], bh[p][2], bh[p][3], base + f.boff + po + koff);
        }
#pragma unroll
        for (int mi = 0; mi < 2; mi++)
#pragma unroll
            for (int ni = 0; ni < 8; ni++) {
                int p = ni >> 1, q = (ni & 1) * 2;
                mma16816(acc[mi][ni], ah[mi], bh[p][q], bh[p][q + 1]);
                mma16816(acc[mi][ni], al[mi], bh[p][q], bh[p][q + 1]);
            }
    }
}

// ---------------------------------------------------------------------------
// GEMM1 + fused SiLU*up.  B tile: rows 0-63 = gate cols, rows 64-127 = up cols.
// grid: (CAP/128, FFN/64, NE).  Writes act as fp16 hi/lo to g_Ahi/g_Alo.
// ---------------------------------------------------------------------------
#define NKB1 (HID / 32)
__global__ void __launch_bounds__(256, 1) gemm1_kernel() {
    extern __shared__ char smem[];
    int e = blockIdx.z;
    int cnt = g_count[e];
    int row0 = blockIdx.x * 128;
    if (row0 >= cnt) return;
    int col0 = blockIdx.y * 64;          // act column base

    int tid = threadIdx.x;
    uint32_t sb = smem_u32(smem);

    int lrow = tid >> 1, h = tid & 1;
    int tokA = g_tok[e * CAP + min(row0 + lrow, cnt - 1)];
    const __half* sAh = g_Xhi + (size_t)tokA * HID + h * 16;
    const __half* sAl = g_Xlo + (size_t)tokA * HID + h * 16;
    size_t wr = (lrow < 64) ? ((size_t)e * FFN2 + col0 + lrow)
                            : ((size_t)e * FFN2 + FFN + col0 + (lrow - 64));
    const __half* sB = g_W1h + wr * HID + h * 16;
    uint32_t dsto = (uint32_t)(lrow * (SROW * 2) + h * 32);

#define G1_ISSUE(kb)                                                          \
    do {                                                                      \
        if ((kb) < NKB1) {                                                    \
            uint32_t d = sb + ((kb) % NSTG) * SBUF + dsto;                    \
            int k0 = (kb) * 32;                                               \
            cpa16(d,             sAh + k0); cpa16(d + 16,             sAh + k0 + 8); \
            cpa16(d + TILEB,     sAl + k0); cpa16(d + TILEB + 16,     sAl + k0 + 8); \
            cpa16(d + 2 * TILEB, sB  + k0); cpa16(d + 2 * TILEB + 16, sB  + k0 + 8); \
        }                                                                     \
        CP_COMMIT();                                                          \
    } while (0)

    G1_ISSUE(0);
    G1_ISSUE(1);

    FragAddr f = frag_addrs(tid);
    float acc[2][8][4];
#pragma unroll
    for (int mi = 0; mi < 2; mi++)
#pragma unroll
        for (int ni = 0; ni < 8; ni++)
#pragma unroll
            for (int q = 0; q < 4; q++) acc[mi][ni][q] = 0.f;

    for (int kb = 0; kb < NKB1; kb++) {
        G1_ISSUE(kb + 2);
        CP_WAIT2();
        __syncthreads();
        compute_kb(sb + (kb % NSTG) * SBUF, f, acc);
        __syncthreads();
    }
#undef G1_ISSUE

    // ---- fused activation epilogue via smem exchange ----
    CP_WAIT0();
    __syncthreads();
    float* sf = (float*)smem;
    {
        int lane = tid & 31, wid = tid >> 5;
        int wm = wid >> 1, wn = wid & 1;
        int gid = lane >> 2, t4 = lane & 3;
#pragma unroll
        for (int mi = 0; mi < 2; mi++) {
            int r = wm * 32 + mi * 16 + gid;
#pragma unroll
            for (int ni = 0; ni < 8; ni++) {
                int c = wn * 64 + ni * 8 + 2 * t4;
                sf[r * ROWF + c]     = acc[mi][ni][0];
                sf[r * ROWF + c + 1] = acc[mi][ni][1];
                sf[(r + 8) * ROWF + c]     = acc[mi][ni][2];
                sf[(r + 8) * ROWF + c + 1] = acc[mi][ni][3];
            }
        }
    }
    __syncthreads();
    {
        int r = tid >> 1, hh = tid & 1;
        int grow = row0 + r;
        if (grow < cnt) {
            uint32_t ph[16], pl[16];
#pragma unroll
            for (int j = 0; j < 32; j += 2) {
                int c = hh * 32 + j;
                float g0 = sf[r * ROWF + c],      u0 = sf[r * ROWF + 64 + c];
                float g1 = sf[r * ROWF + c + 1],  u1 = sf[r * ROWF + 64 + c + 1];
                float a0 = g0 / (1.f + __expf(-g0)) * u0;
                float a1 = g1 / (1.f + __expf(-g1)) * u1;
                __half2 hv = __floats2half2_rn(a0, a1);
                float r0 = a0 - __low2float(hv);
                float r1 = a1 - __high2float(hv);
                __half2 lv = __floats2half2_rn(r0, r1);
                ph[j >> 1] = *(uint32_t*)&hv;
                pl[j >> 1] = *(uint32_t*)&lv;
            }
            size_t base = ((size_t)e * CAP + grow) * FFN + col0 + hh * 32;
            uint4* dh = (uint4*)(g_Ahi + base);
            uint4* dl = (uint4*)(g_Alo + base);
#pragma unroll
            for (int q = 0; q < 4; q++) {
                dh[q] = make_uint4(ph[4*q], ph[4*q+1], ph[4*q+2], ph[4*q+3]);
                dl[q] = make_uint4(pl[4*q], pl[4*q+1], pl[4*q+2], pl[4*q+3]);
            }
        }
    }
}

// ---------------------------------------------------------------------------
// GEMM2: y = act @ W2^T -> per-slot g_Y (no atomics).
// ---------------------------------------------------------------------------
#define NKB2 (FFN / 32)
__global__ void __launch_bounds__(256, 1) gemm2_kernel() {
    extern __shared__ char smem[];
    int e = blockIdx.z;
    int cnt = g_count[e];
    int row0 = blockIdx.x * 128;
    if (row0 >= cnt) return;
    int col0 = blockIdx.y * 128;

    int tid = threadIdx.x;
    uint32_t sb = smem_u32(smem);

    int lrow = tid >> 1, h = tid & 1;
    size_t ar = ((size_t)e * CAP + min(row0 + lrow, cnt - 1)) * FFN;
    const __half* sAh = g_Ahi + ar + h * 16;
    const __half* sAl = g_Alo + ar + h * 16;
    const __half* sB  = g_W2h + ((size_t)e * HID + col0 + lrow) * FFN + h * 16;
    uint32_t dsto = (uint32_t)(lrow * (SROW * 2) + h * 32);

#define G2_ISSUE(kb)                                                          \
    do {                                                                      \
        if ((kb) < NKB2) {                                                    \
            uint32_t d = sb + ((kb) % NSTG) * SBUF + dsto;                    \
            int k0 = (kb) * 32;                                               \
            cpa16(d,             sAh + k0); cpa16(d + 16,             sAh + k0 + 8); \
            cpa16(d + TILEB,     sAl + k0); cpa16(d + TILEB + 16,     sAl + k0 + 8); \
            cpa16(d + 2 * TILEB, sB  + k0); cpa16(d + 2 * TILEB + 16, sB  + k0 + 8); \
        }                                                                     \
        CP_COMMIT();                                                          \
    } while (0)

    G2_ISSUE(0);
    G2_ISSUE(1);

    FragAddr f = frag_addrs(tid);
    float acc[2][8][4];
#pragma unroll
    for (int mi = 0; mi < 2; mi++)
#pragma unroll
        for (int ni = 0; ni < 8; ni++)
#pragma unroll
            for (int q = 0; q < 4; q++) acc[mi][ni][q] = 0.f;

    for (int kb = 0; kb < NKB2; kb++) {
        G2_ISSUE(kb + 2);
        CP_WAIT2();
        __syncthreads();
        compute_kb(sb + (kb % NSTG) * SBUF, f, acc);
        __syncthreads();
    }
#undef G2_ISSUE

    int lane = tid & 31, wid = tid >> 5;
    int wm = wid >> 1, wn = wid & 1;
    int gid = lane >> 2, t4 = lane & 3;
#pragma unroll
    for (int mi = 0; mi < 2; mi++) {
        int r0 = row0 + wm * 32 + mi * 16 + gid;
        int r1 = r0 + 8;
        int tok0 = 0, slot0 = 0, tok1 = 0, slot1 = 0;
        if (r0 < cnt) { tok0 = g_tok[e * CAP + r0]; slot0 = g_slot[e * CAP + r0]; }
        if (r1 < cnt) { tok1 = g_tok[e * CAP + r1]; slot1 = g_slot[e * CAP + r1]; }
#pragma unroll
        for (int ni = 0; ni < 8; ni++) {
            int col = col0 + wn * 64 + ni * 8 + 2 * t4;
            if (r0 < cnt) {
                float2 v = make_float2(acc[mi][ni][0], acc[mi][ni][1]);
                *(float2*)(g_Y + ((size_t)slot0 * SEQ + tok0) * HID + col) = v;
            }
            if (r1 < cnt) {
                float2 v = make_float2(acc[mi][ni][2], acc[mi][ni][3]);
                *(float2*)(g_Y + ((size_t)slot1 * SEQ + tok1) * HID + col) = v;
            }
        }
    }
}

// ---------------------------------------------------------------------------
__global__ void combine_kernel(float4* __restrict__ out) {
    const float4* y = (const float4*)g_Y;
    size_t n = (size_t)SEQ * HID / 4;
    for (size_t i = (size_t)blockIdx.x * blockDim.x + threadIdx.x; i < n;
         i += (size_t)gridDim.x * blockDim.x) {
        int t = (int)(i >> 9);   // HID/4 = 512 float4 per token
        float w0 = g_twt[t * 2 + 0];
        float w1 = g_twt[t * 2 + 1];
        float4 a = y[i];
        float4 b = y[i + n];
        float4 o;
        o.x = w0 * a.x + w1 * b.x;
        o.y = w0 * a.y + w1 * b.y;
        o.z = w0 * a.z + w1 * b.z;
        o.w = w0 * a.w + w1 * b.w;
        out[i] = o;
    }
}

// ---------------------------------------------------------------------------
extern "C" void kernel_launch(void* const* d_in, const int* in_sizes, int n_in,
                              void* d_out, int out_size) {
    const float* X  = (const float*)d_in[0];
    const float* G  = (const float*)d_in[1];
    const float* W1 = (const float*)d_in[2];
    const float* W2 = (const float*)d_in[3];
    float* out = (float*)d_out;

    bool has_logits = (long long)out_size >= (long long)SEQ * HID + (long long)SEQ * NE;
    float* logits = has_logits ? out + (size_t)SEQ * HID : nullptr;

    cudaFuncSetAttribute(gemm1_kernel, cudaFuncAttributeMaxDynamicSharedMemorySize, GSMEM);
    cudaFuncSetAttribute(gemm2_kernel, cudaFuncAttributeMaxDynamicSharedMemorySize, GSMEM);

    reset_kernel<<<1, 32>>>();
    router_kernel<<<SEQ / 8, 256>>>(X, G, logits);
    splitx_kernel<<<2048, 256>>>((const float4*)X, (size_t)SEQ * HID / 4);
    conv_kernel<<<4096, 256>>>((const float4*)W1, (size_t)NE * FFN2 * HID / 4, 1);
    conv_kernel<<<4096, 256>>>((const float4*)W2, (size_t)NE * HID * FFN / 4, 2);
    gemm1_kernel<<<dim3(CAP / 128, FFN / 64, NE), 256, GSMEM>>>();
    gemm2_kernel<<<dim3(CAP / 128, HID / 128, NE), 256, GSMEM>>>();
    combine_kernel<<<4096, 256>>>((float4*)out);
}

// round 7
// speedup vs baseline: 4.2016x; 1.3633x over previous
#include <cuda_runtime.h>
#include <cuda_fp16.h>
#include <cstdint>
#include <math.h>

#define SEQ   4096
#define HID   2048
#define NE    8
#define FFN   1408
#define FFN2  2816
#define CAP   4096

// ---------------- static scratch ----------------
__device__ int   g_count[NE];
__device__ int   g_tok [NE * CAP];
__device__ int   g_slot[NE * CAP];
__device__ float g_twt [SEQ * 2];

__device__ __half g_Xhi[(size_t)SEQ * HID];
__device__ __half g_Xlo[(size_t)SEQ * HID];
__device__ __half g_W1h[(size_t)NE * FFN2 * HID];
__device__ __half g_W2h[(size_t)NE * HID * FFN];
__device__ __half g_Ahi[(size_t)NE * CAP * FFN];
__device__ float  g_Y  [(size_t)2 * SEQ * HID];

// ---------------- helpers ----------------
__device__ __forceinline__ uint32_t smem_u32(const void* p) {
    uint32_t a;
    asm("{ .reg .u64 t; cvta.to.shared.u64 t, %1; cvt.u32.u64 %0, t; }"
        : "=r"(a) : "l"(p));
    return a;
}
__device__ __forceinline__ void cpa16(uint32_t dst, const void* src) {
    asm volatile("cp.async.cg.shared.global [%0], [%1], 16;" :: "r"(dst), "l"(src));
}
#define CP_COMMIT() asm volatile("cp.async.commit_group;" ::: "memory")
#define CP_WAIT1()  asm volatile("cp.async.wait_group 1;" ::: "memory")
#define CP_WAIT2()  asm volatile("cp.async.wait_group 2;" ::: "memory")
#define CP_WAIT0()  asm volatile("cp.async.wait_group 0;" ::: "memory")

__device__ __forceinline__ void ldsm4(uint32_t& r0, uint32_t& r1, uint32_t& r2,
                                      uint32_t& r3, uint32_t addr) {
    asm volatile("ldmatrix.sync.aligned.m8n8.x4.shared.b16 {%0,%1,%2,%3}, [%4];"
                 : "=r"(r0), "=r"(r1), "=r"(r2), "=r"(r3) : "r"(addr));
}
__device__ __forceinline__ void mma16816(float* c, const uint32_t* a,
                                         uint32_t b0, uint32_t b1) {
    asm volatile(
        "mma.sync.aligned.m16n8k16.row.col.f32.f16.f16.f32 "
        "{%0,%1,%2,%3}, {%4,%5,%6,%7}, {%8,%9}, {%0,%1,%2,%3};"
        : "+f"(c[0]), "+f"(c[1]), "+f"(c[2]), "+f"(c[3])
        : "r"(a[0]), "r"(a[1]), "r"(a[2]), "r"(a[3]), "r"(b0), "r"(b1));
}

// smem tile: 128 rows x 32 k, padded to 40 halves (80B) per row
#define SROW   40
#define TILEB  (128 * SROW * 2)    // 10240 B
// GEMM1: 3 stages x (Ah, Al, B)
#define SBUF1  (3 * TILEB)
#define NSTG1  3
#define GSMEM1 (NSTG1 * SBUF1)     // 92160 B
// GEMM2: 4 stages x (Ah, B)
#define SBUF2  (2 * TILEB)
#define NSTG2  4
#define GSMEM2 (NSTG2 * SBUF2)     // 81920 B
#define ROWF   132                  // f32 scratch row stride (GEMM1 epilogue)

// ---------------------------------------------------------------------------
__global__ void reset_kernel() {
    if (threadIdx.x < NE) g_count[threadIdx.x] = 0;
}

// ---------------------------------------------------------------------------
__global__ void splitx_kernel(const float4* __restrict__ src, size_t n4) {
    uint2* dh = (uint2*)g_Xhi;
    uint2* dl = (uint2*)g_Xlo;
    for (size_t i = (size_t)blockIdx.x * blockDim.x + threadIdx.x; i < n4;
         i += (size_t)gridDim.x * blockDim.x) {
        float4 v = src[i];
        __half2 h01 = __floats2half2_rn(v.x, v.y);
        __half2 h23 = __floats2half2_rn(v.z, v.w);
        float rx = v.x - __low2float(h01);
        float ry = v.y - __high2float(h01);
        float rz = v.z - __low2float(h23);
        float rw = v.w - __high2float(h23);
        __half2 l01 = __floats2half2_rn(rx, ry);
        __half2 l23 = __floats2half2_rn(rz, rw);
        uint2 uh, ul;
        uh.x = *(uint32_t*)&h01; uh.y = *(uint32_t*)&h23;
        ul.x = *(uint32_t*)&l01; ul.y = *(uint32_t*)&l23;
        dh[i] = uh; dl[i] = ul;
    }
}

__global__ void conv_kernel(const float4* __restrict__ src, size_t n4, int which) {
    uint2* dst = (uint2*)(which == 1 ? g_W1h : g_W2h);
    for (size_t i = (size_t)blockIdx.x * blockDim.x + threadIdx.x; i < n4;
         i += (size_t)gridDim.x * blockDim.x) {
        float4 v = src[i];
        __half2 h01 = __floats2half2_rn(v.x, v.y);
        __half2 h23 = __floats2half2_rn(v.z, v.w);
        uint2 u;
        u.x = *(uint32_t*)&h01; u.y = *(uint32_t*)&h23;
        dst[i] = u;
    }
}

// ---------------------------------------------------------------------------
__global__ void router_kernel(const float* __restrict__ X,
                              const float* __restrict__ G,
                              float* __restrict__ out_logits) {
    int warp = (blockIdx.x * blockDim.x + threadIdx.x) >> 5;
    int lane = threadIdx.x & 31;
    if (warp >= SEQ) return;

    const float* x = X + (size_t)warp * HID;
    float acc[NE];
#pragma unroll
    for (int e = 0; e < NE; e++) acc[e] = 0.f;
    for (int h = lane; h < HID; h += 32) {
        float xv = x[h];
        const float* g = G + (size_t)h * NE;
#pragma unroll
        for (int e = 0; e < NE; e++) acc[e] += xv * g[e];
    }
#pragma unroll
    for (int e = 0; e < NE; e++)
#pragma unroll
        for (int o = 16; o > 0; o >>= 1)
            acc[e] += __shfl_xor_sync(0xFFFFFFFFu, acc[e], o);

    if (lane == 0) {
        if (out_logits) {
#pragma unroll
            for (int e = 0; e < NE; e++) out_logits[warp * NE + e] = acc[e];
        }
        float m = acc[0];
#pragma unroll
        for (int e = 1; e < NE; e++) m = fmaxf(m, acc[e]);
        float p[NE];
#pragma unroll
        for (int e = 0; e < NE; e++) p[e] = __expf(acc[e] - m);
        int i1 = 0;
#pragma unroll
        for (int e = 1; e < NE; e++) if (p[e] > p[i1]) i1 = e;
        int i2 = (i1 == 0) ? 1 : 0;
#pragma unroll
        for (int e = 0; e < NE; e++)
            if (e != i1 && p[e] > p[i2]) i2 = e;
        float tot = p[i1] + p[i2];
        g_twt[warp * 2 + 0] = p[i1] / tot;
        g_twt[warp * 2 + 1] = p[i2] / tot;
        int s1 = atomicAdd(&g_count[i1], 1);
        g_tok [i1 * CAP + s1] = warp;
        g_slot[i1 * CAP + s1] = 0;
        int s2 = atomicAdd(&g_count[i2], 1);
        g_tok [i2 * CAP + s2] = warp;
        g_slot[i2 * CAP + s2] = 1;
    }
}

// ---------------------------------------------------------------------------
// Warp/frag mapping (CTA 128x128, 8 warps, warp tile 32x64)
// ---------------------------------------------------------------------------
struct FragAddr { uint32_t aoff, boff; };
__device__ __forceinline__ FragAddr frag_addrs(int tid, uint32_t btile_off) {
    int lane = tid & 31, wid = tid >> 5;
    int wm = wid >> 1, wn = wid & 1;
    int t = lane >> 3, l7 = lane & 7;
    FragAddr f;
    f.aoff = (uint32_t)((wm * 32 + (t & 1) * 8 + l7) * (SROW * 2) + (t >> 1) * 16);
    f.boff = (uint32_t)((wn * 64 + (t >> 1) * 8 + l7) * (SROW * 2) + (t & 1) * 16)
             + btile_off;
    return f;
}

// k-block compute, A = hi+lo (2 MMAs)
__device__ __forceinline__ void compute_kb2(uint32_t base, const FragAddr& f,
                                            float acc[2][8][4]) {
#pragma unroll
    for (int k16 = 0; k16 < 2; k16++) {
        uint32_t koff = k16 * 32;
        uint32_t ah[2][4], al[2][4];
        ldsm4(ah[0][0], ah[0][1], ah[0][2], ah[0][3], base + f.aoff + koff);
        ldsm4(ah[1][0], ah[1][1], ah[1][2], ah[1][3], base + f.aoff + koff + 16 * SROW * 2);
        ldsm4(al[0][0], al[0][1], al[0][2], al[0][3], base + TILEB + f.aoff + koff);
        ldsm4(al[1][0], al[1][1], al[1][2], al[1][3], base + TILEB + f.aoff + koff + 16 * SROW * 2);
        uint32_t bh[4][4];
#pragma unroll
        for (int p = 0; p < 4; p++) {
            uint32_t po = p * 16 * SROW * 2;
            ldsm4(bh[p][0], bh[p][1], bh[p][2], bh[p][3], base + f.boff + po + koff);
        }
#pragma unroll
        for (int mi = 0; mi < 2; mi++)
#pragma unroll
            for (int ni = 0; ni < 8; ni++) {
                int p = ni >> 1, q = (ni & 1) * 2;
                mma16816(acc[mi][ni], ah[mi], bh[p][q], bh[p][q + 1]);
                mma16816(acc[mi][ni], al[mi], bh[p][q], bh[p][q + 1]);
            }
    }
}

// k-block compute, A = hi only (1 MMA)
__device__ __forceinline__ void compute_kb1(uint32_t base, const FragAddr& f,
                                            float acc[2][8][4]) {
#pragma unroll
    for (int k16 = 0; k16 < 2; k16++) {
        uint32_t koff = k16 * 32;
        uint32_t ah[2][4];
        ldsm4(ah[0][0], ah[0][1], ah[0][2], ah[0][3], base + f.aoff + koff);
        ldsm4(ah[1][0], ah[1][1], ah[1][2], ah[1][3], base + f.aoff + koff + 16 * SROW * 2);
        uint32_t bh[4][4];
#pragma unroll
        for (int p = 0; p < 4; p++) {
            uint32_t po = p * 16 * SROW * 2;
            ldsm4(bh[p][0], bh[p][1], bh[p][2], bh[p][3], base + f.boff + po + koff);
        }
#pragma unroll
        for (int mi = 0; mi < 2; mi++)
#pragma unroll
            for (int ni = 0; ni < 8; ni++) {
                int p = ni >> 1, q = (ni & 1) * 2;
                mma16816(acc[mi][ni], ah[mi], bh[p][q], bh[p][q + 1]);
            }
    }
}

// ---------------------------------------------------------------------------
// GEMM1 + fused SiLU*up.  B tile rows 0-63 = gate, 64-127 = up.
// grid (CAP/128, FFN/64, NE). X = hi+lo. One __syncthreads per k-block.
// ---------------------------------------------------------------------------
#define NKB1 (HID / 32)
__global__ void __launch_bounds__(256, 1) gemm1_kernel() {
    extern __shared__ char smem[];
    int e = blockIdx.z;
    int cnt = g_count[e];
    int row0 = blockIdx.x * 128;
    if (row0 >= cnt) return;
    int col0 = blockIdx.y * 64;

    int tid = threadIdx.x;
    uint32_t sb = smem_u32(smem);

    int lrow = tid >> 1, h = tid & 1;
    int tokA = g_tok[e * CAP + min(row0 + lrow, cnt - 1)];
    const __half* sAh = g_Xhi + (size_t)tokA * HID + h * 16;
    const __half* sAl = g_Xlo + (size_t)tokA * HID + h * 16;
    size_t wr = (lrow < 64) ? ((size_t)e * FFN2 + col0 + lrow)
                            : ((size_t)e * FFN2 + FFN + col0 + (lrow - 64));
    const __half* sB = g_W1h + wr * HID + h * 16;
    uint32_t dsto = (uint32_t)(lrow * (SROW * 2) + h * 32);

#define G1_ISSUE(kb)                                                          \
    do {                                                                      \
        if ((kb) < NKB1) {                                                    \
            uint32_t d = sb + ((kb) % NSTG1) * SBUF1 + dsto;                  \
            int k0 = (kb) * 32;                                               \
            cpa16(d,             sAh + k0); cpa16(d + 16,             sAh + k0 + 8); \
            cpa16(d + TILEB,     sAl + k0); cpa16(d + TILEB + 16,     sAl + k0 + 8); \
            cpa16(d + 2 * TILEB, sB  + k0); cpa16(d + 2 * TILEB + 16, sB  + k0 + 8); \
        }                                                                     \
        CP_COMMIT();                                                          \
    } while (0)

    G1_ISSUE(0);
    G1_ISSUE(1);

    FragAddr f = frag_addrs(tid, 2 * TILEB);
    float acc[2][8][4];
#pragma unroll
    for (int mi = 0; mi < 2; mi++)
#pragma unroll
        for (int ni = 0; ni < 8; ni++)
#pragma unroll
            for (int q = 0; q < 4; q++) acc[mi][ni][q] = 0.f;

    // iter kb: wait(group kb done) -> sync -> compute(kb) -> issue(kb+2)
    // issue targets stage (kb+2)%3 == (kb-1)%3; compute(kb-1) completed by
    // all warps before this iteration's sync => WAR-safe with ONE sync.
    for (int kb = 0; kb < NKB1; kb++) {
        CP_WAIT1();
        __syncthreads();
        compute_kb2(sb + (kb % NSTG1) * SBUF1, f, acc);
        G1_ISSUE(kb + 2);
    }
#undef G1_ISSUE

    // ---- fused activation epilogue via smem exchange ----
    CP_WAIT0();
    __syncthreads();
    float* sf = (float*)smem;
    {
        int lane = tid & 31, wid = tid >> 5;
        int wm = wid >> 1, wn = wid & 1;
        int gid = lane >> 2, t4 = lane & 3;
#pragma unroll
        for (int mi = 0; mi < 2; mi++) {
            int r = wm * 32 + mi * 16 + gid;
#pragma unroll
            for (int ni = 0; ni < 8; ni++) {
                int c = wn * 64 + ni * 8 + 2 * t4;
                sf[r * ROWF + c]     = acc[mi][ni][0];
                sf[r * ROWF + c + 1] = acc[mi][ni][1];
                sf[(r + 8) * ROWF + c]     = acc[mi][ni][2];
                sf[(r + 8) * ROWF + c + 1] = acc[mi][ni][3];
            }
        }
    }
    __syncthreads();
    {
        int r = tid >> 1, hh = tid & 1;
        int grow = row0 + r;
        if (grow < cnt) {
            uint32_t ph[16];
#pragma unroll
            for (int j = 0; j < 32; j += 2) {
                int c = hh * 32 + j;
                float g0 = sf[r * ROWF + c],      u0 = sf[r * ROWF + 64 + c];
                float g1 = sf[r * ROWF + c + 1],  u1 = sf[r * ROWF + 64 + c + 1];
                float a0 = g0 / (1.f + __expf(-g0)) * u0;
                float a1 = g1 / (1.f + __expf(-g1)) * u1;
                __half2 hv = __floats2half2_rn(a0, a1);
                ph[j >> 1] = *(uint32_t*)&hv;
            }
            size_t base = ((size_t)e * CAP + grow) * FFN + col0 + hh * 32;
            uint4* dh = (uint4*)(g_Ahi + base);
#pragma unroll
            for (int q = 0; q < 4; q++)
                dh[q] = make_uint4(ph[4*q], ph[4*q+1], ph[4*q+2], ph[4*q+3]);
        }
    }
}

// ---------------------------------------------------------------------------
// GEMM2: y = act_hi @ W2^T -> per-slot g_Y. 4 stages, 3-deep prefetch.
// ---------------------------------------------------------------------------
#define NKB2 (FFN / 32)
__global__ void __launch_bounds__(256, 1) gemm2_kernel() {
    extern __shared__ char smem[];
    int e = blockIdx.z;
    int cnt = g_count[e];
    int row0 = blockIdx.x * 128;
    if (row0 >= cnt) return;
    int col0 = blockIdx.y * 128;

    int tid = threadIdx.x;
    uint32_t sb = smem_u32(smem);

    int lrow = tid >> 1, h = tid & 1;
    size_t ar = ((size_t)e * CAP + min(row0 + lrow, cnt - 1)) * FFN;
    const __half* sAh = g_Ahi + ar + h * 16;
    const __half* sB  = g_W2h + ((size_t)e * HID + col0 + lrow) * FFN + h * 16;
    uint32_t dsto = (uint32_t)(lrow * (SROW * 2) + h * 32);

#define G2_ISSUE(kb)                                                          \
    do {                                                                      \
        if ((kb) < NKB2) {                                                    \
            uint32_t d = sb + ((kb) % NSTG2) * SBUF2 + dsto;                  \
            int k0 = (kb) * 32;                                               \
            cpa16(d,         sAh + k0); cpa16(d + 16,         sAh + k0 + 8);  \
            cpa16(d + TILEB, sB  + k0); cpa16(d + TILEB + 16, sB  + k0 + 8);  \
        }                                                                     \
        CP_COMMIT();                                                          \
    } while (0)

    G2_ISSUE(0);
    G2_ISSUE(1);
    G2_ISSUE(2);

    FragAddr f = frag_addrs(tid, TILEB);
    float acc[2][8][4];
#pragma unroll
    for (int mi = 0; mi < 2; mi++)
#pragma unroll
        for (int ni = 0; ni < 8; ni++)
#pragma unroll
            for (int q = 0; q < 4; q++) acc[mi][ni][q] = 0.f;

    // iter kb: wait(<=2 pending => group kb done) -> sync -> compute -> issue(kb+3)
    // issue stage (kb+3)%4 == (kb-1)%4; compute(kb-1) done before this sync.
    for (int kb = 0; kb < NKB2; kb++) {
        CP_WAIT2();
        __syncthreads();
        compute_kb1(sb + (kb % NSTG2) * SBUF2, f, acc);
        G2_ISSUE(kb + 3);
    }
#undef G2_ISSUE

    int lane = tid & 31, wid = tid >> 5;
    int wm = wid >> 1, wn = wid & 1;
    int gid = lane >> 2, t4 = lane & 3;
#pragma unroll
    for (int mi = 0; mi < 2; mi++) {
        int r0 = row0 + wm * 32 + mi * 16 + gid;
        int r1 = r0 + 8;
        int tok0 = 0, slot0 = 0, tok1 = 0, slot1 = 0;
        if (r0 < cnt) { tok0 = g_tok[e * CAP + r0]; slot0 = g_slot[e * CAP + r0]; }
        if (r1 < cnt) { tok1 = g_tok[e * CAP + r1]; slot1 = g_slot[e * CAP + r1]; }
#pragma unroll
        for (int ni = 0; ni < 8; ni++) {
            int col = col0 + wn * 64 + ni * 8 + 2 * t4;
            if (r0 < cnt) {
                float2 v = make_float2(acc[mi][ni][0], acc[mi][ni][1]);
                *(float2*)(g_Y + ((size_t)slot0 * SEQ + tok0) * HID + col) = v;
            }
            if (r1 < cnt) {
                float2 v = make_float2(acc[mi][ni][2], acc[mi][ni][3]);
                *(float2*)(g_Y + ((size_t)slot1 * SEQ + tok1) * HID + col) = v;
            }
        }
    }
}

// ---------------------------------------------------------------------------
__global__ void combine_kernel(float4* __restrict__ out) {
    const float4* y = (const float4*)g_Y;
    size_t n = (size_t)SEQ * HID / 4;
    for (size_t i = (size_t)blockIdx.x * blockDim.x + threadIdx.x; i < n;
         i += (size_t)gridDim.x * blockDim.x) {
        int t = (int)(i >> 9);
        float w0 = g_twt[t * 2 + 0];
        float w1 = g_twt[t * 2 + 1];
        float4 a = y[i];
        float4 b = y[i + n];
        float4 o;
        o.x = w0 * a.x + w1 * b.x;
        o.y = w0 * a.y + w1 * b.y;
        o.z = w0 * a.z + w1 * b.z;
        o.w = w0 * a.w + w1 * b.w;
        out[i] = o;
    }
}

// ---------------------------------------------------------------------------
extern "C" void kernel_launch(void* const* d_in, const int* in_sizes, int n_in,
                              void* d_out, int out_size) {
    const float* X  = (const float*)d_in[0];
    const float* G  = (const float*)d_in[1];
    const float* W1 = (const float*)d_in[2];
    const float* W2 = (const float*)d_in[3];
    float* out = (float*)d_out;

    bool has_logits = (long long)out_size >= (long long)SEQ * HID + (long long)SEQ * NE;
    float* logits = has_logits ? out + (size_t)SEQ * HID : nullptr;

    cudaFuncSetAttribute(gemm1_kernel, cudaFuncAttributeMaxDynamicSharedMemorySize, GSMEM1);
    cudaFuncSetAttribute(gemm2_kernel, cudaFuncAttributeMaxDynamicSharedMemorySize, GSMEM2);

    reset_kernel<<<1, 32>>>();
    router_kernel<<<SEQ / 8, 256>>>(X, G, logits);
    splitx_kernel<<<2048, 256>>>((const float4*)X, (size_t)SEQ * HID / 4);
    conv_kernel<<<4096, 256>>>((const float4*)W1, (size_t)NE * FFN2 * HID / 4, 1);
    conv_kernel<<<4096, 256>>>((const float4*)W2, (size_t)NE * HID * FFN / 4, 2);
    gemm1_kernel<<<dim3(CAP / 128, FFN / 64, NE), 256, GSMEM1>>>();
    gemm2_kernel<<<dim3(CAP / 128, HID / 128, NE), 256, GSMEM2>>>();
    combine_kernel<<<4096, 256>>>((float4*)out);
}

// round 8
// speedup vs baseline: 5.9876x; 1.4251x over previous
#include <cuda_runtime.h>
#include <cuda_fp16.h>
#include <cstdint>
#include <math.h>

#define SEQ   4096
#define HID   2048
#define NE    8
#define FFN   1408
#define FFN2  2816
#define CAP   4096

// ---------------- static scratch ----------------
__device__ int   g_count[NE];
__device__ int   g_tok [NE * CAP];
__device__ int   g_slot[NE * CAP];
__device__ float g_twt [SEQ * 2];

__device__ __half g_Xh [(size_t)SEQ * HID];
__device__ __half g_W1h[(size_t)NE * FFN2 * HID];
__device__ __half g_W2h[(size_t)NE * HID * FFN];
__device__ __half g_Ah [(size_t)NE * CAP * FFN];
__device__ float  g_Y  [(size_t)2 * SEQ * HID];

// ---------------- helpers ----------------
__device__ __forceinline__ uint32_t smem_u32(const void* p) {
    uint32_t a;
    asm("{ .reg .u64 t; cvta.to.shared.u64 t, %1; cvt.u32.u64 %0, t; }"
        : "=r"(a) : "l"(p));
    return a;
}
__device__ __forceinline__ void cpa16(uint32_t dst, const void* src) {
    asm volatile("cp.async.cg.shared.global [%0], [%1], 16;" :: "r"(dst), "l"(src));
}
#define CP_COMMIT() asm volatile("cp.async.commit_group;" ::: "memory")
#define CP_WAIT2()  asm volatile("cp.async.wait_group 2;" ::: "memory")
#define CP_WAIT0()  asm volatile("cp.async.wait_group 0;" ::: "memory")

__device__ __forceinline__ void ldsm4(uint32_t& r0, uint32_t& r1, uint32_t& r2,
                                      uint32_t& r3, uint32_t addr) {
    asm volatile("ldmatrix.sync.aligned.m8n8.x4.shared.b16 {%0,%1,%2,%3}, [%4];"
                 : "=r"(r0), "=r"(r1), "=r"(r2), "=r"(r3) : "r"(addr));
}
__device__ __forceinline__ void mma16816(float* c, const uint32_t* a,
                                         uint32_t b0, uint32_t b1) {
    asm volatile(
        "mma.sync.aligned.m16n8k16.row.col.f32.f16.f16.f32 "
        "{%0,%1,%2,%3}, {%4,%5,%6,%7}, {%8,%9}, {%0,%1,%2,%3};"
        : "+f"(c[0]), "+f"(c[1]), "+f"(c[2]), "+f"(c[3])
        : "r"(a[0]), "r"(a[1]), "r"(a[2]), "r"(a[3]), "r"(b0), "r"(b1));
}

// smem tile: 128 rows x 32 k, padded to 40 halves (80B) per row
#define SROW   40
#define TILEB  (128 * SROW * 2)    // 10240 B
#define SBUF   (2 * TILEB)         // (A, B) per stage = 20480 B
#define NSTG   4
#define GSMEM  (NSTG * SBUF)       // 81920 B  (2 CTAs/SM)
#define ROWF   132                  // f32 scratch row stride (GEMM1 epilogue)

// ---------------------------------------------------------------------------
__global__ void reset_kernel() {
    if (threadIdx.x < NE) g_count[threadIdx.x] = 0;
}

// fp32 -> fp16 round; which: 0=X, 1=W1, 2=W2
__global__ void conv_kernel(const float4* __restrict__ src, size_t n4, int which) {
    uint2* dst = (uint2*)(which == 0 ? g_Xh : (which == 1 ? g_W1h : g_W2h));
    for (size_t i = (size_t)blockIdx.x * blockDim.x + threadIdx.x; i < n4;
         i += (size_t)gridDim.x * blockDim.x) {
        float4 v = src[i];
        __half2 h01 = __floats2half2_rn(v.x, v.y);
        __half2 h23 = __floats2half2_rn(v.z, v.w);
        uint2 u;
        u.x = *(uint32_t*)&h01; u.y = *(uint32_t*)&h23;
        dst[i] = u;
    }
}

// ---------------------------------------------------------------------------
__global__ void router_kernel(const float* __restrict__ X,
                              const float* __restrict__ G,
                              float* __restrict__ out_logits) {
    int warp = (blockIdx.x * blockDim.x + threadIdx.x) >> 5;
    int lane = threadIdx.x & 31;
    if (warp >= SEQ) return;

    const float* x = X + (size_t)warp * HID;
    float acc[NE];
#pragma unroll
    for (int e = 0; e < NE; e++) acc[e] = 0.f;
    for (int h = lane; h < HID; h += 32) {
        float xv = x[h];
        const float* g = G + (size_t)h * NE;
#pragma unroll
        for (int e = 0; e < NE; e++) acc[e] += xv * g[e];
    }
#pragma unroll
    for (int e = 0; e < NE; e++)
#pragma unroll
        for (int o = 16; o > 0; o >>= 1)
            acc[e] += __shfl_xor_sync(0xFFFFFFFFu, acc[e], o);

    if (lane == 0) {
        if (out_logits) {
#pragma unroll
            for (int e = 0; e < NE; e++) out_logits[warp * NE + e] = acc[e];
        }
        float m = acc[0];
#pragma unroll
        for (int e = 1; e < NE; e++) m = fmaxf(m, acc[e]);
        float p[NE];
#pragma unroll
        for (int e = 0; e < NE; e++) p[e] = __expf(acc[e] - m);
        int i1 = 0;
#pragma unroll
        for (int e = 1; e < NE; e++) if (p[e] > p[i1]) i1 = e;
        int i2 = (i1 == 0) ? 1 : 0;
#pragma unroll
        for (int e = 0; e < NE; e++)
            if (e != i1 && p[e] > p[i2]) i2 = e;
        float tot = p[i1] + p[i2];
        g_twt[warp * 2 + 0] = p[i1] / tot;
        g_twt[warp * 2 + 1] = p[i2] / tot;
        int s1 = atomicAdd(&g_count[i1], 1);
        g_tok [i1 * CAP + s1] = warp;
        g_slot[i1 * CAP + s1] = 0;
        int s2 = atomicAdd(&g_count[i2], 1);
        g_tok [i2 * CAP + s2] = warp;
        g_slot[i2 * CAP + s2] = 1;
    }
}

// ---------------------------------------------------------------------------
// Warp/frag mapping (CTA 128x128, 8 warps, warp tile 32x64); B tile at +TILEB
// ---------------------------------------------------------------------------
struct FragAddr { uint32_t aoff, boff; };
__device__ __forceinline__ FragAddr frag_addrs(int tid) {
    int lane = tid & 31, wid = tid >> 5;
    int wm = wid >> 1, wn = wid & 1;
    int t = lane >> 3, l7 = lane & 7;
    FragAddr f;
    f.aoff = (uint32_t)((wm * 32 + (t & 1) * 8 + l7) * (SROW * 2) + (t >> 1) * 16);
    f.boff = (uint32_t)((wn * 64 + (t >> 1) * 8 + l7) * (SROW * 2) + (t & 1) * 16)
             + TILEB;
    return f;
}

__device__ __forceinline__ void compute_kb(uint32_t base, const FragAddr& f,
                                           float acc[2][8][4]) {
#pragma unroll
    for (int k16 = 0; k16 < 2; k16++) {
        uint32_t koff = k16 * 32;
        uint32_t ah[2][4];
        ldsm4(ah[0][0], ah[0][1], ah[0][2], ah[0][3], base + f.aoff + koff);
        ldsm4(ah[1][0], ah[1][1], ah[1][2], ah[1][3], base + f.aoff + koff + 16 * SROW * 2);
        uint32_t bh[4][4];
#pragma unroll
        for (int p = 0; p < 4; p++) {
            uint32_t po = p * 16 * SROW * 2;
            ldsm4(bh[p][0], bh[p][1], bh[p][2], bh[p][3], base + f.boff + po + koff);
        }
#pragma unroll
        for (int mi = 0; mi < 2; mi++)
#pragma unroll
            for (int ni = 0; ni < 8; ni++) {
                int p = ni >> 1, q = (ni & 1) * 2;
                mma16816(acc[mi][ni], ah[mi], bh[p][q], bh[p][q + 1]);
            }
    }
}

// ---------------------------------------------------------------------------
// GEMM1 + fused SiLU*up.  B tile rows 0-63 = gate, 64-127 = up.
// grid (CAP/128, FFN/64, NE).
// ---------------------------------------------------------------------------
#define NKB1 (HID / 32)
__global__ void __launch_bounds__(256, 2) gemm1_kernel() {
    extern __shared__ char smem[];
    int e = blockIdx.z;
    int cnt = g_count[e];
    int row0 = blockIdx.x * 128;
    if (row0 >= cnt) return;
    int col0 = blockIdx.y * 64;

    int tid = threadIdx.x;
    uint32_t sb = smem_u32(smem);

    int lrow = tid >> 1, h = tid & 1;
    int tokA = g_tok[e * CAP + min(row0 + lrow, cnt - 1)];
    const __half* sA = g_Xh + (size_t)tokA * HID + h * 16;
    size_t wr = (lrow < 64) ? ((size_t)e * FFN2 + col0 + lrow)
                            : ((size_t)e * FFN2 + FFN + col0 + (lrow - 64));
    const __half* sB = g_W1h + wr * HID + h * 16;
    uint32_t dsto = (uint32_t)(lrow * (SROW * 2) + h * 32);

#define G1_ISSUE(kb)                                                          \
    do {                                                                      \
        if ((kb) < NKB1) {                                                    \
            uint32_t d = sb + ((kb) % NSTG) * SBUF + dsto;                    \
            int k0 = (kb) * 32;                                               \
            cpa16(d,         sA + k0); cpa16(d + 16,         sA + k0 + 8);    \
            cpa16(d + TILEB, sB + k0); cpa16(d + TILEB + 16, sB + k0 + 8);    \
        }                                                                     \
        CP_COMMIT();                                                          \
    } while (0)

    G1_ISSUE(0);
    G1_ISSUE(1);
    G1_ISSUE(2);

    FragAddr f = frag_addrs(tid);
    float acc[2][8][4];
#pragma unroll
    for (int mi = 0; mi < 2; mi++)
#pragma unroll
        for (int ni = 0; ni < 8; ni++)
#pragma unroll
            for (int q = 0; q < 4; q++) acc[mi][ni][q] = 0.f;

    // iter kb: wait(<=2 pending => group kb done) -> sync -> compute -> issue(kb+3)
    // issue targets stage (kb+3)%4 == (kb-1)%4, whose compute finished before
    // this iteration's sync => WAR-safe with one sync per k-block.
    for (int kb = 0; kb < NKB1; kb++) {
        CP_WAIT2();
        __syncthreads();
        compute_kb(sb + (kb % NSTG) * SBUF, f, acc);
        G1_ISSUE(kb + 3);
    }
#undef G1_ISSUE

    // ---- fused activation epilogue via smem exchange ----
    CP_WAIT0();
    __syncthreads();
    float* sf = (float*)smem;
    {
        int lane = tid & 31, wid = tid >> 5;
        int wm = wid >> 1, wn = wid & 1;
        int gid = lane >> 2, t4 = lane & 3;
#pragma unroll
        for (int mi = 0; mi < 2; mi++) {
            int r = wm * 32 + mi * 16 + gid;
#pragma unroll
            for (int ni = 0; ni < 8; ni++) {
                int c = wn * 64 + ni * 8 + 2 * t4;
                sf[r * ROWF + c]     = acc[mi][ni][0];
                sf[r * ROWF + c + 1] = acc[mi][ni][1];
                sf[(r + 8) * ROWF + c]     = acc[mi][ni][2];
                sf[(r + 8) * ROWF + c + 1] = acc[mi][ni][3];
            }
        }
    }
    __syncthreads();
    {
        int r = tid >> 1, hh = tid & 1;
        int grow = row0 + r;
        if (grow < cnt) {
            uint32_t ph[16];
#pragma unroll
            for (int j = 0; j < 32; j += 2) {
                int c = hh * 32 + j;
                float g0 = sf[r * ROWF + c],      u0 = sf[r * ROWF + 64 + c];
                float g1 = sf[r * ROWF + c + 1],  u1 = sf[r * ROWF + 64 + c + 1];
                float a0 = g0 / (1.f + __expf(-g0)) * u0;
                float a1 = g1 / (1.f + __expf(-g1)) * u1;
                __half2 hv = __floats2half2_rn(a0, a1);
                ph[j >> 1] = *(uint32_t*)&hv;
            }
            size_t base = ((size_t)e * CAP + grow) * FFN + col0 + hh * 32;
            uint4* dh = (uint4*)(g_Ah + base);
#pragma unroll
            for (int q = 0; q < 4; q++)
                dh[q] = make_uint4(ph[4*q], ph[4*q+1], ph[4*q+2], ph[4*q+3]);
        }
    }
}

// ---------------------------------------------------------------------------
// GEMM2: y = act @ W2^T -> per-slot g_Y.
// ---------------------------------------------------------------------------
#define NKB2 (FFN / 32)
__global__ void __launch_bounds__(256, 2) gemm2_kernel() {
    extern __shared__ char smem[];
    int e = blockIdx.z;
    int cnt = g_count[e];
    int row0 = blockIdx.x * 128;
    if (row0 >= cnt) return;
    int col0 = blockIdx.y * 128;

    int tid = threadIdx.x;
    uint32_t sb = smem_u32(smem);

    int lrow = tid >> 1, h = tid & 1;
    size_t ar = ((size_t)e * CAP + min(row0 + lrow, cnt - 1)) * FFN;
    const __half* sA = g_Ah + ar + h * 16;
    const __half* sB = g_W2h + ((size_t)e * HID + col0 + lrow) * FFN + h * 16;
    uint32_t dsto = (uint32_t)(lrow * (SROW * 2) + h * 32);

#define G2_ISSUE(kb)                                                          \
    do {                                                                      \
        if ((kb) < NKB2) {                                                    \
            uint32_t d = sb + ((kb) % NSTG) * SBUF + dsto;                    \
            int k0 = (kb) * 32;                                               \
            cpa16(d,         sA + k0); cpa16(d + 16,         sA + k0 + 8);    \
            cpa16(d + TILEB, sB + k0); cpa16(d + TILEB + 16, sB + k0 + 8);    \
        }                                                                     \
        CP_COMMIT();                                                          \
    } while (0)

    G2_ISSUE(0);
    G2_ISSUE(1);
    G2_ISSUE(2);

    FragAddr f = frag_addrs(tid);
    float acc[2][8][4];
#pragma unroll
    for (int mi = 0; mi < 2; mi++)
#pragma unroll
        for (int ni = 0; ni < 8; ni++)
#pragma unroll
            for (int q = 0; q < 4; q++) acc[mi][ni][q] = 0.f;

    for (int kb = 0; kb < NKB2; kb++) {
        CP_WAIT2();
        __syncthreads();
        compute_kb(sb + (kb % NSTG) * SBUF, f, acc);
        G2_ISSUE(kb + 3);
    }
#undef G2_ISSUE

    int lane = tid & 31, wid = tid >> 5;
    int wm = wid >> 1, wn = wid & 1;
    int gid = lane >> 2, t4 = lane & 3;
#pragma unroll
    for (int mi = 0; mi < 2; mi++) {
        int r0 = row0 + wm * 32 + mi * 16 + gid;
        int r1 = r0 + 8;
        int tok0 = 0, slot0 = 0, tok1 = 0, slot1 = 0;
        if (r0 < cnt) { tok0 = g_tok[e * CAP + r0]; slot0 = g_slot[e * CAP + r0]; }
        if (r1 < cnt) { tok1 = g_tok[e * CAP + r1]; slot1 = g_slot[e * CAP + r1]; }
#pragma unroll
        for (int ni = 0; ni < 8; ni++) {
            int col = col0 + wn * 64 + ni * 8 + 2 * t4;
            if (r0 < cnt) {
                float2 v = make_float2(acc[mi][ni][0], acc[mi][ni][1]);
                *(float2*)(g_Y + ((size_t)slot0 * SEQ + tok0) * HID + col) = v;
            }
            if (r1 < cnt) {
                float2 v = make_float2(acc[mi][ni][2], acc[mi][ni][3]);
                *(float2*)(g_Y + ((size_t)slot1 * SEQ + tok1) * HID + col) = v;
            }
        }
    }
}

// ---------------------------------------------------------------------------
__global__ void combine_kernel(float4* __restrict__ out) {
    const float4* y = (const float4*)g_Y;
    size_t n = (size_t)SEQ * HID / 4;
    for (size_t i = (size_t)blockIdx.x * blockDim.x + threadIdx.x; i < n;
         i += (size_t)gridDim.x * blockDim.x) {
        int t = (int)(i >> 9);
        float w0 = g_twt[t * 2 + 0];
        float w1 = g_twt[t * 2 + 1];
        float4 a = y[i];
        float4 b = y[i + n];
        float4 o;
        o.x = w0 * a.x + w1 * b.x;
        o.y = w0 * a.y + w1 * b.y;
        o.z = w0 * a.z + w1 * b.z;
        o.w = w0 * a.w + w1 * b.w;
        out[i] = o;
    }
}

// ---------------------------------------------------------------------------
extern "C" void kernel_launch(void* const* d_in, const int* in_sizes, int n_in,
                              void* d_out, int out_size) {
    const float* X  = (const float*)d_in[0];
    const float* G  = (const float*)d_in[1];
    const float* W1 = (const float*)d_in[2];
    const float* W2 = (const float*)d_in[3];
    float* out = (float*)d_out;

    bool has_logits = (long long)out_size >= (long long)SEQ * HID + (long long)SEQ * NE;
    float* logits = has_logits ? out + (size_t)SEQ * HID : nullptr;

    cudaFuncSetAttribute(gemm1_kernel, cudaFuncAttributeMaxDynamicSharedMemorySize, GSMEM);
    cudaFuncSetAttribute(gemm2_kernel, cudaFuncAttributeMaxDynamicSharedMemorySize, GSMEM);

    reset_kernel<<<1, 32>>>();
    router_kernel<<<SEQ / 8, 256>>>(X, G, logits);
    conv_kernel<<<2048, 256>>>((const float4*)X,  (size_t)SEQ * HID / 4, 0);
    conv_kernel<<<4096, 256>>>((const float4*)W1, (size_t)NE * FFN2 * HID / 4, 1);
    conv_kernel<<<4096, 256>>>((const float4*)W2, (size_t)NE * HID * FFN / 4, 2);
    gemm1_kernel<<<dim3(CAP / 128, FFN / 64, NE), 256, GSMEM>>>();
    gemm2_kernel<<<dim3(CAP / 128, HID / 128, NE), 256, GSMEM>>>();
    combine_kernel<<<4096, 256>>>((float4*)out);
}